// round 17
// baseline (speedup 1.0000x reference)
#include <cuda_runtime.h>

#define BB 512
#define TT 1024
#define IDIM 64
#define HH 10
#define G4 40      // 4*H
#define NCHUNK 4   // 4 chunks of 256 timesteps per batch
#define NLSTMB 128 // lstm-role blocks (512 warps)

typedef unsigned long long u64;

// Scratch (static device globals — no runtime allocation)
// XG layout per row: unit-interleaved pairs, u64 index p2 (0..19):
//   p2 = 2k   -> (i_k, f_k) preacts, PRE-SCALED by 0.5
//   p2 = 2k+1 -> (g_k, o_k) preacts, g unscaled, o PRE-SCALED by 0.5
__device__ float d_XG1[BB * TT * G4];
__device__ float d_XG2[BB * TT * G4];
__device__ volatile int d_flag[BB * NCHUNK];   // chunk-ready flags

// position p = 4*u + gt (gt: 0=i,1=f,2=g,3=o) -> original PyTorch gate row
__device__ __forceinline__ int old_gate(int p) {
    int u = p >> 2, gt = p & 3;
    return gt * HH + u;
}

__device__ __forceinline__ float tanh_ap(float x) {
    float y;
    asm("tanh.approx.f32 %0, %1;" : "=f"(y) : "f"(x));
    return y;
}

// ---- packed f32x2 helpers (sm_100+) ----
__device__ __forceinline__ u64 pk2(float lo, float hi) {
    u64 r; asm("mov.b64 %0, {%1, %2};" : "=l"(r) : "f"(lo), "f"(hi)); return r;
}
__device__ __forceinline__ void upk2(float& lo, float& hi, u64 v) {
    asm("mov.b64 {%0, %1}, %2;" : "=f"(lo), "=f"(hi) : "l"(v));
}
__device__ __forceinline__ u64 fma2(u64 a, u64 b, u64 c) {
    u64 d; asm("fma.rn.f32x2 %0, %1, %2, %3;" : "=l"(d) : "l"(a), "l"(b), "l"(c)); return d;
}
__device__ __forceinline__ u64 mul2(u64 a, u64 b) {
    u64 d; asm("mul.rn.f32x2 %0, %1, %2;" : "=l"(d) : "l"(a), "l"(b)); return d;
}
__device__ __forceinline__ u64 add2(u64 a, u64 b) {
    u64 d; asm("add.rn.f32x2 %0, %1, %2;" : "=l"(d) : "l"(a), "l"(b)); return d;
}

__device__ __forceinline__ void waitflag(int idx) {
    while (!d_flag[idx]) __nanosleep(64);
    __threadfence();   // acquire
}

__global__ void k_zeroflags() {
    int i = blockIdx.x * blockDim.x + threadIdx.x;
    if (i < BB * NCHUNK) d_flag[i] = 0;
}

// ---------------------------------------------------------------------------
// smem broadcast: lanes 0-9 store (hb,hb); all lanes read 5x LDS.128.
// bufp must be 16B-aligned. Double-buffered by the caller (step parity).
// ---------------------------------------------------------------------------
#define BCAST_SM(hb, hv, bufp)                                                \
    {                                                                         \
        if (klow) ((u64*)(bufp))[k2] = pk2(hb, hb);                           \
        __syncwarp();                                                         \
        const ulonglong2* _b2 = reinterpret_cast<const ulonglong2*>(bufp);    \
        ulonglong2 _q0 = _b2[0], _q1 = _b2[1], _q2 = _b2[2];                  \
        ulonglong2 _q3 = _b2[3], _q4 = _b2[4];                                \
        hv[0] = _q0.x; hv[1] = _q0.y; hv[2] = _q1.x; hv[3] = _q1.y;           \
        hv[4] = _q2.x; hv[5] = _q2.y; hv[6] = _q3.x; hv[7] = _q3.y;           \
        hv[8] = _q4.x; hv[9] = _q4.y;                                         \
    }

// ---------------------------------------------------------------------------
// lstm step macros (R16-proven math; broadcast via smem)
// ---------------------------------------------------------------------------
#define STEP1(hb, cc, hv, ab, outp, sidx, bufp)                               \
    {                                                                         \
        u64 t1 = gemmrole ? bIF : (ab).x;                                     \
        u64 t2 = gemmrole ? bGO : (ab).y;                                     \
        u64 e1 = fma2(wa[0], hv[0], t1);                                      \
        e1 = fma2(wa[2], hv[2], e1);                                          \
        e1 = fma2(wa[4], hv[4], e1);                                          \
        e1 = fma2(wa[6], hv[6], e1);                                          \
        e1 = fma2(wa[8], hv[8], e1);                                          \
        u64 o1 = mul2(wa[1], hv[1]);                                          \
        o1 = fma2(wa[3], hv[3], o1);                                          \
        o1 = fma2(wa[5], hv[5], o1);                                          \
        o1 = fma2(wa[7], hv[7], o1);                                          \
        o1 = fma2(wa[9], hv[9], o1);                                          \
        u64 g1 = add2(e1, o1);                                                \
        u64 e2 = fma2(wb[0], hv[0], t2);                                      \
        e2 = fma2(wb[2], hv[2], e2);                                          \
        e2 = fma2(wb[4], hv[4], e2);                                          \
        e2 = fma2(wb[6], hv[6], e2);                                          \
        e2 = fma2(wb[8], hv[8], e2);                                          \
        u64 o2 = mul2(wb[1], hv[1]);                                          \
        o2 = fma2(wb[3], hv[3], o2);                                          \
        o2 = fma2(wb[5], hv[5], o2);                                          \
        o2 = fma2(wb[7], hv[7], o2);                                          \
        o2 = fma2(wb[9], hv[9], o2);                                          \
        u64 g2 = add2(e2, o2);                                                \
        if (gemmrole && (sidx) >= 0) {                                        \
            ulonglong2 v; v.x = g1; v.y = g2;                                 \
            (outp)[(size_t)(sidx) * HH] = v;                                  \
        }                                                                     \
        float xi, xf, xg, xo;                                                 \
        upk2(xi, xf, g1);                                                     \
        upk2(xg, xo, g2);                                                     \
        float ti = tanh_ap(xi);                                               \
        float tf = tanh_ap(xf);                                               \
        float tg = tanh_ap(xg);                                               \
        float to_ = tanh_ap(xo);                                              \
        float u_ = fmaf(tf, cc, cc);                                          \
        float v_ = fmaf(ti, tg, tg);                                          \
        cc = 0.5f * (u_ + v_);                                                \
        float tc = tanh_ap(cc);                                               \
        hb = fmaf(to_, tc, tc);                                               \
        BCAST_SM(hb, hv, bufp);                                               \
    }

#define GEMM_TAIL(hv, outp)                                                   \
    {                                                                         \
        u64 e1 = fma2(wa[0], hv[0], bIF);                                     \
        e1 = fma2(wa[2], hv[2], e1);                                          \
        e1 = fma2(wa[4], hv[4], e1);                                          \
        e1 = fma2(wa[6], hv[6], e1);                                          \
        e1 = fma2(wa[8], hv[8], e1);                                          \
        u64 o1 = mul2(wa[1], hv[1]);                                          \
        o1 = fma2(wa[3], hv[3], o1);                                          \
        o1 = fma2(wa[5], hv[5], o1);                                          \
        o1 = fma2(wa[7], hv[7], o1);                                          \
        o1 = fma2(wa[9], hv[9], o1);                                          \
        u64 g1 = add2(e1, o1);                                                \
        u64 e2 = fma2(wb[0], hv[0], bGO);                                     \
        e2 = fma2(wb[2], hv[2], e2);                                          \
        e2 = fma2(wb[4], hv[4], e2);                                          \
        e2 = fma2(wb[6], hv[6], e2);                                          \
        e2 = fma2(wb[8], hv[8], e2);                                          \
        u64 o2 = mul2(wb[1], hv[1]);                                          \
        o2 = fma2(wb[3], hv[3], o2);                                          \
        o2 = fma2(wb[5], hv[5], o2);                                          \
        o2 = fma2(wb[7], hv[7], o2);                                          \
        o2 = fma2(wb[9], hv[9], o2);                                          \
        u64 g2 = add2(e2, o2);                                                \
        if (gemmrole) {                                                       \
            ulonglong2 v; v.x = g1; v.y = g2;                                 \
            (outp)[(size_t)(TT - 1) * HH] = v;                                \
        }                                                                     \
    }

#define STEP2(hb, cc, hv, ab, bufp)                                           \
    {                                                                         \
        u64 e1 = fma2(wa[0], hv[0], (ab).x);                                  \
        e1 = fma2(wa[2], hv[2], e1);                                          \
        e1 = fma2(wa[4], hv[4], e1);                                          \
        e1 = fma2(wa[6], hv[6], e1);                                          \
        e1 = fma2(wa[8], hv[8], e1);                                          \
        u64 o1 = mul2(wa[1], hv[1]);                                          \
        o1 = fma2(wa[3], hv[3], o1);                                          \
        o1 = fma2(wa[5], hv[5], o1);                                          \
        o1 = fma2(wa[7], hv[7], o1);                                          \
        o1 = fma2(wa[9], hv[9], o1);                                          \
        u64 g1 = add2(e1, o1);                                                \
        u64 e2 = fma2(wb[0], hv[0], (ab).y);                                  \
        e2 = fma2(wb[2], hv[2], e2);                                          \
        e2 = fma2(wb[4], hv[4], e2);                                          \
        e2 = fma2(wb[6], hv[6], e2);                                          \
        e2 = fma2(wb[8], hv[8], e2);                                          \
        u64 o2 = mul2(wb[1], hv[1]);                                          \
        o2 = fma2(wb[3], hv[3], o2);                                          \
        o2 = fma2(wb[5], hv[5], o2);                                          \
        o2 = fma2(wb[7], hv[7], o2);                                          \
        o2 = fma2(wb[9], hv[9], o2);                                          \
        u64 g2 = add2(e2, o2);                                                \
        float xi, xf, xg, xo;                                                 \
        upk2(xi, xf, g1);                                                     \
        upk2(xg, xo, g2);                                                     \
        float ti = tanh_ap(xi);                                               \
        float tf = tanh_ap(xf);                                               \
        float tg = tanh_ap(xg);                                               \
        float to_ = tanh_ap(xo);                                              \
        float u_ = fmaf(tf, cc, cc);                                          \
        float v_ = fmaf(ti, tg, tg);                                          \
        cc = 0.5f * (u_ + v_);                                                \
        float tc = tanh_ap(cc);                                               \
        hb = fmaf(to_, tc, tc);                                               \
        BCAST_SM(hb, hv, bufp);                                               \
    }

// ---------------------------------------------------------------------------
// Fused kernel. Blocks 0..127: lstm role (4 warps, 1 batch each; both layers
// + FC, h/c carried in registers). Blocks 128..2175: K1 role (quarter-batch
// each, chunk-major order; publishes d_flag[b*4+c]). K1 never waits.
// ---------------------------------------------------------------------------
__global__ __launch_bounds__(128) void k_fused(
    const float* __restrict__ x,      // [B*T, 64]
    const float* __restrict__ Wih1,   // [40, 64]
    const float* __restrict__ bih1,
    const float* __restrict__ bhh1,
    const float* __restrict__ Whh1,   // [40,10]
    const float* __restrict__ h0,
    const float* __restrict__ c0,
    const float* __restrict__ Wih2,   // [40,10]
    const float* __restrict__ bih2,
    const float* __restrict__ bhh2,
    const float* __restrict__ Whh2,   // [40,10]
    const float* __restrict__ fc1w,
    const float* __restrict__ fc1b,
    const float* __restrict__ fc2w,   // [1024]
    const float* __restrict__ fc2b,
    float* __restrict__ out)          // [B]
{
    __shared__ u64 sW[64 * 20];
    __shared__ u64 sB[20];
    __shared__ __align__(16) u64 sH[4][2][12];   // per-warp double-buffered h bcast
    int tid = threadIdx.x;

    if (blockIdx.x >= NLSTMB) {
        // ================= K1 role (proven 98us math; 128 thr, 256 rows) ===
        int krank = blockIdx.x - NLSTMB;   // 0..2047
        int chunk = krank >> 9;            // chunk-major
        int batch = krank & 511;

        for (int e = tid; e < 64 * 20; e += 128) {
            int k = e / 20, p2 = e % 20;
            float slo = (p2 & 1) ? 1.0f : 0.5f;
            float lo = slo * Wih1[old_gate(2 * p2) * 64 + k];
            float hi = 0.5f * Wih1[old_gate(2 * p2 + 1) * 64 + k];
            sW[e] = pk2(lo, hi);
        }
        for (int e = tid; e < 20; e += 128) {
            float slo = (e & 1) ? 1.0f : 0.5f;
            int oA = old_gate(2 * e), oB = old_gate(2 * e + 1);
            sB[e] = pk2(slo * (bih1[oA] + bhh1[oA]), 0.5f * (bih1[oB] + bhh1[oB]));
        }
        __syncthreads();

        int q = tid & 3;
        int rb = tid >> 2;
        size_t r0 = (size_t)batch * TT + (size_t)chunk * 256 + (size_t)rb * 8;

        u64 acc[8][5];
#pragma unroll
        for (int r = 0; r < 8; r++)
#pragma unroll
            for (int j = 0; j < 5; j++) acc[r][j] = sB[q + 4 * j];

        const float4* x4 = reinterpret_cast<const float4*>(x);
#pragma unroll 2
        for (int kk = 0; kk < 16; kk++) {
            float4 xv[8];
#pragma unroll
            for (int r = 0; r < 8; r++) xv[r] = x4[(r0 + r) * 16 + kk];
#pragma unroll
            for (int c = 0; c < 4; c++) {
                u64 xd[8];
#pragma unroll
                for (int r = 0; r < 8; r++) {
                    float xc = (c == 0) ? xv[r].x : (c == 1) ? xv[r].y
                             : (c == 2) ? xv[r].z : xv[r].w;
                    xd[r] = pk2(xc, xc);
                }
#pragma unroll
                for (int j = 0; j < 5; j++) {
                    u64 w = sW[(4 * kk + c) * 20 + q + 4 * j];
#pragma unroll
                    for (int r = 0; r < 8; r++)
                        acc[r][j] = fma2(w, xd[r], acc[r][j]);
                }
            }
        }
#pragma unroll
        for (int r = 0; r < 8; r++) {
            u64* orow = reinterpret_cast<u64*>(d_XG1 + (r0 + r) * G4);
#pragma unroll
            for (int j = 0; j < 5; j++) orow[q + 4 * j] = acc[r][j];
        }

        __threadfence();
        __syncthreads();
        if (tid == 0) d_flag[batch * NCHUNK + chunk] = 1;
        return;
    }

    // ================= lstm role: 4 warps, one batch each ==================
    int lane = tid & 31;
    int wid = tid >> 5;
    int batch = blockIdx.x * 4 + wid;
    int k2 = lane % HH;
    bool gemmrole = (lane >= 10 && lane < 20);
    bool klow = lane < HH;

    u64* buf0 = &sH[wid][0][0];
    u64* buf1 = &sH[wid][1][0];

    // ---- pass 1: layer-1 recurrence + fused layer-2 input gemm ----
    const float* Wsel = gemmrole ? Wih2 : Whh1;
    u64 wa[10], wb[10];
#pragma unroll
    for (int j = 0; j < 10; j++) {
        wa[j] = pk2(0.25f * Wsel[(0 * HH + k2) * HH + j],
                    0.25f * Wsel[(1 * HH + k2) * HH + j]);
        wb[j] = pk2(0.50f * Wsel[(2 * HH + k2) * HH + j],
                    0.25f * Wsel[(3 * HH + k2) * HH + j]);
    }
    u64 bIF = pk2(0.5f * (bih2[0 * HH + k2] + bhh2[0 * HH + k2]),
                  0.5f * (bih2[1 * HH + k2] + bhh2[1 * HH + k2]));
    u64 bGO = pk2(1.0f * (bih2[2 * HH + k2] + bhh2[2 * HH + k2]),
                  0.5f * (bih2[3 * HH + k2] + bhh2[3 * HH + k2]));

    float hb = 2.0f * h0[batch * HH + k2];
    float cc = c0[batch * HH + k2];
    u64 hv[10];
    BCAST_SM(hb, hv, buf1);   // initial broadcast (uses buf1; loop starts buf0)

    const ulonglong2* base =
        reinterpret_cast<const ulonglong2*>(d_XG1) + (size_t)batch * TT * HH + k2;
    ulonglong2* outp =
        reinterpret_cast<ulonglong2*>(d_XG2) + (size_t)batch * TT * HH + k2;

    waitflag(batch * NCHUNK);          // chunk 0 ready

    ulonglong2 cur[4], nxt[4];
#pragma unroll
    for (int i = 0; i < 4; i++) cur[i] = base[i * HH];
#pragma unroll
    for (int i = 0; i < 4; i++) nxt[i] = base[(4 + i) * HH];

    for (int t = 0; t < TT; t += 4) {
        ulonglong2 pf[4];
        if (t + 8 < TT) {
            if (((t + 8) & 255) == 0)
                waitflag(batch * NCHUNK + ((t + 8) >> 8));
#pragma unroll
            for (int i = 0; i < 4; i++) pf[i] = base[(size_t)(t + 8 + i) * HH];
        }
        STEP1(hb, cc, hv, cur[0], outp, t - 1, buf0);
        STEP1(hb, cc, hv, cur[1], outp, t,     buf1);
        STEP1(hb, cc, hv, cur[2], outp, t + 1, buf0);
        STEP1(hb, cc, hv, cur[3], outp, t + 2, buf1);
#pragma unroll
        for (int i = 0; i < 4; i++) { cur[i] = nxt[i]; nxt[i] = pf[i]; }
    }
    GEMM_TAIL(hv, outp);

    __threadfence_block();
    __syncwarp();

    // ---- pass 2: layer-2 recurrence + fused FC (state carried in regs) ----
#pragma unroll
    for (int j = 0; j < 10; j++) {
        wa[j] = pk2(0.25f * Whh2[(0 * HH + k2) * HH + j],
                    0.25f * Whh2[(1 * HH + k2) * HH + j]);
        wb[j] = pk2(0.50f * Whh2[(2 * HH + k2) * HH + j],
                    0.25f * Whh2[(3 * HH + k2) * HH + j]);
    }
    BCAST_SM(hb, hv, buf1);

    const ulonglong2* base2 =
        reinterpret_cast<const ulonglong2*>(d_XG2) + (size_t)batch * TT * HH + k2;
    const float4* f4 = reinterpret_cast<const float4*>(fc2w);

    ulonglong2 cur2[4], nxt2[4];
#pragma unroll
    for (int i = 0; i < 4; i++) cur2[i] = base2[i * HH];
#pragma unroll
    for (int i = 0; i < 4; i++) nxt2[i] = base2[(4 + i) * HH];

    float acc = 0.0f;   // sum_t hbig * fc2w[t]
    float s2 = 0.0f;    // sum_t fc2w[t]

    for (int t = 0; t < TT; t += 4) {
        ulonglong2 pf[4];
        if (t + 8 < TT) {
#pragma unroll
            for (int i = 0; i < 4; i++) pf[i] = base2[(size_t)(t + 8 + i) * HH];
        }
        float4 fwv = __ldg(&f4[t >> 2]);
        STEP2(hb, cc, hv, cur2[0], buf0);
        acc = fmaf(hb, fwv.x, acc);
        STEP2(hb, cc, hv, cur2[1], buf1);
        acc = fmaf(hb, fwv.y, acc);
        STEP2(hb, cc, hv, cur2[2], buf0);
        acc = fmaf(hb, fwv.z, acc);
        STEP2(hb, cc, hv, cur2[3], buf1);
        acc = fmaf(hb, fwv.w, acc);
        s2 += (fwv.x + fwv.y) + (fwv.z + fwv.w);
#pragma unroll
        for (int i = 0; i < 4; i++) { cur2[i] = nxt2[i]; nxt2[i] = pf[i]; }
    }

    // acc holds 2*sum(h*fw) -> scale fc1w by 0.5; lanes >=10 contribute 0.
    float val = klow ? acc * (0.5f * fc1w[k2]) : 0.0f;
#pragma unroll
    for (int off = 16; off > 0; off >>= 1)
        val += __shfl_xor_sync(0xffffffffu, val, off);
    if (lane == 0)
        out[batch] = val + fc1b[0] * s2 + fc2b[0];
}

// ---------------------------------------------------------------------------
extern "C" void kernel_launch(void* const* d_in, const int* in_sizes, int n_in,
                              void* d_out, int out_size)
{
    const float* x    = (const float*)d_in[0];
    const float* h0   = (const float*)d_in[1];
    const float* c0   = (const float*)d_in[2];
    const float* Wih1 = (const float*)d_in[3];
    const float* Whh1 = (const float*)d_in[4];
    const float* bih1 = (const float*)d_in[5];
    const float* bhh1 = (const float*)d_in[6];
    const float* Wih2 = (const float*)d_in[7];
    const float* Whh2 = (const float*)d_in[8];
    const float* bih2 = (const float*)d_in[9];
    const float* bhh2 = (const float*)d_in[10];
    const float* fc1w = (const float*)d_in[11];
    const float* fc1b = (const float*)d_in[12];
    const float* fc2w = (const float*)d_in[13];
    const float* fc2b = (const float*)d_in[14];
    float* out = (float*)d_out;

    k_zeroflags<<<16, 128>>>();
    k_fused<<<NLSTMB + 2048, 128>>>(
        x, Wih1, bih1, bhh1, Whh1, h0, c0,
        Wih2, bih2, bhh2, Whh2, fc1w, fc1b, fc2w, fc2b, out);
}